// round 1
// baseline (speedup 1.0000x reference)
#include <cuda_runtime.h>
#include <math.h>

#define HH 16
#define WW 16
#define HWX 256
#define CC 64
#define PP 48
#define GG 48
#define NPAIR (PP*GG)
#define EPSV 1e-5

// Scratch (no allocations allowed)
__device__ double g_sum_d;
__device__ double g_sumsq_d;
__device__ float  g_dot[NPAIR];

__global__ void zero_kernel() {
    g_sum_d = 0.0;
    g_sumsq_d = 0.0;
}

__device__ __forceinline__ double warpRedD(double v) {
    #pragma unroll
    for (int o = 16; o > 0; o >>= 1)
        v += __shfl_xor_sync(0xffffffffu, v, o);
    return v;
}

extern __shared__ float smem[];

// One block per (p,g) pair. 256 threads.
// C[r,s] = sum_c gal[g][c][r] * prob[p][c][s]   (256x256, K=64)
// s2[r] = max over hc in win(hr(r)), all wc, of C[r, hc*16+wc]
// s1[s] = max over hr in win(hc(s)), all wr, of C[hr*16+wr, s]
__global__ __launch_bounds__(256)
void pair_kernel(const float* __restrict__ prob, const float* __restrict__ gal,
                 const float* __restrict__ fc_w) {
    float* As = smem;                       // gal tile  [64][256]
    float* Bs = smem + CC * HWX;            // prob tile [64][256]
    float* m2 = smem + 2 * CC * HWX;        // [256][16] : per-row r, per-hc-group max
    float* m1 = m2 + 256 * 16;              // [16][256] : per-hr-group, per-col s max

    const int blk = blockIdx.x;
    const int ip = blk / GG;
    const int ig = blk % GG;
    const int tid = threadIdx.x;
    const int tx = tid & 15;
    const int ty = tid >> 4;

    // Stage both operand tiles (coalesced float4)
    {
        const float4* gsrc = (const float4*)(gal + (size_t)ig * CC * HWX);
        const float4* psrc = (const float4*)(prob + (size_t)ip * CC * HWX);
        float4* As4 = (float4*)As;
        float4* Bs4 = (float4*)Bs;
        #pragma unroll
        for (int i = 0; i < 16; i++) {
            As4[tid + i * 256] = gsrc[tid + i * 256];
            Bs4[tid + i * 256] = psrc[tid + i * 256];
        }
    }
    __syncthreads();

    // Four 128x128 quarters; each thread owns an 8x8 tile per quarter.
    #pragma unroll
    for (int rh = 0; rh < 2; rh++) {
        #pragma unroll
        for (int sh = 0; sh < 2; sh++) {
            float acc[8][8];
            #pragma unroll
            for (int i = 0; i < 8; i++)
                #pragma unroll
                for (int j = 0; j < 8; j++)
                    acc[i][j] = 0.0f;

            const int rbase = rh * 128 + ty * 8;
            const int sbase = sh * 128 + tx * 8;

            #pragma unroll 4
            for (int k = 0; k < CC; k++) {
                float4 a0 = *(const float4*)&As[k * HWX + rbase];
                float4 a1 = *(const float4*)&As[k * HWX + rbase + 4];
                float4 b0 = *(const float4*)&Bs[k * HWX + sbase];
                float4 b1 = *(const float4*)&Bs[k * HWX + sbase + 4];
                float a[8] = {a0.x, a0.y, a0.z, a0.w, a1.x, a1.y, a1.z, a1.w};
                float b[8] = {b0.x, b0.y, b0.z, b0.w, b1.x, b1.y, b1.z, b1.w};
                #pragma unroll
                for (int i = 0; i < 8; i++)
                    #pragma unroll
                    for (int j = 0; j < 8; j++)
                        acc[i][j] = fmaf(a[i], b[j], acc[i][j]);
            }

            // Per-row max over this thread's 8 cols; combine tx-pair (lane^1)
            // to get max over full 16-col hc group. Disjoint writes per quarter.
            #pragma unroll
            for (int i = 0; i < 8; i++) {
                float rm = acc[i][0];
                #pragma unroll
                for (int j = 1; j < 8; j++) rm = fmaxf(rm, acc[i][j]);
                float o = __shfl_xor_sync(0xffffffffu, rm, 1);
                rm = fmaxf(rm, o);
                if ((tx & 1) == 0)
                    m2[(rbase + i) * 16 + sh * 8 + (tx >> 1)] = rm;
            }

            // Per-col max over this thread's 8 rows; combine ty-pair (lane^16)
            // to get max over full 16-row hr group.
            #pragma unroll
            for (int j = 0; j < 8; j++) {
                float cm = acc[0][j];
                #pragma unroll
                for (int i = 1; i < 8; i++) cm = fmaxf(cm, acc[i][j]);
                float o = __shfl_xor_sync(0xffffffffu, cm, 16);
                cm = fmaxf(cm, o);
                if ((ty & 1) == 0)
                    m1[(rh * 8 + (ty >> 1)) * HWX + sbase + j] = cm;
            }
        }
    }
    __syncthreads();

    // Windowed max: window = 4 consecutive blocks, u = clamp(i-2, 0, 12)
    const int hb = tid >> 4;              // hr(r) for r=tid, == hc(s) for s=tid
    const int u = min(max(hb - 2, 0), 12);

    float s2v = -3.4e38f;                 // r = tid
    #pragma unroll
    for (int t = 0; t < 4; t++) s2v = fmaxf(s2v, m2[tid * 16 + u + t]);

    float s1v = -3.4e38f;                 // s = tid
    #pragma unroll
    for (int t = 0; t < 4; t++) s1v = fmaxf(s1v, m1[(u + t) * HWX + tid]);

    const float wv = fc_w[tid];
    double dsum = (double)s1v + (double)s2v;
    double dsq  = (double)s1v * s1v + (double)s2v * s2v;
    double ddot = (double)wv * ((double)s1v + (double)s2v);

    dsum = warpRedD(dsum);
    dsq  = warpRedD(dsq);
    ddot = warpRedD(ddot);

    __syncthreads();                      // done reading m1/m2 -> reuse as reduce buf
    double* sred = (double*)m2;
    const int wid = tid >> 5, lane = tid & 31;
    if (lane == 0) {
        sred[wid] = dsum;
        sred[8 + wid] = dsq;
        sred[16 + wid] = ddot;
    }
    __syncthreads();
    if (tid == 0) {
        double s = 0, q = 0, d = 0;
        #pragma unroll
        for (int i = 0; i < 8; i++) { s += sred[i]; q += sred[8 + i]; d += sred[16 + i]; }
        atomicAdd(&g_sum_d, s);
        atomicAdd(&g_sumsq_d, q);
        g_dot[blk] = (float)d;
    }
}

// Single block, 256 threads. Applies BN -> fc -> pair-sum -> lbn -> sigmoid.
// fc(BN(x)) row = a*(x.w) + (-a*m*Wsum + beta*Wsum + b), a = gamma*rsqrt(v+eps);
// pair-sum of the two rows -> pre = a*dot + 2*(-a*m*Wsum + beta*Wsum + b).
__global__ __launch_bounds__(256)
void finalize_kernel(const float* __restrict__ bn_gamma, const float* __restrict__ bn_beta,
                     const float* __restrict__ fc_w, const float* __restrict__ fc_b,
                     const float* __restrict__ lbn_gamma, const float* __restrict__ lbn_beta,
                     float* __restrict__ out) {
    __shared__ double sred[24];
    __shared__ double bcast[4];
    const int tid = threadIdx.x;
    const int wid = tid >> 5, lane = tid & 31;

    // Wsum
    double wv = (double)fc_w[tid];
    wv = warpRedD(wv);
    if (lane == 0) sred[wid] = wv;
    __syncthreads();
    if (tid == 0) {
        double s = 0;
        #pragma unroll
        for (int i = 0; i < 8; i++) s += sred[i];
        bcast[0] = s;
    }
    __syncthreads();
    const double Wsum = bcast[0];

    const double N1 = 2.0 * (double)NPAIR * (double)HWX;
    const double m = g_sum_d / N1;
    const double v = g_sumsq_d / N1 - m * m;
    const double a = (double)bn_gamma[0] * rsqrt(v + EPSV);
    const double cst = 2.0 * (-a * m * Wsum + (double)bn_beta[0] * Wsum + (double)fc_b[0]);

    float pre[9];
    double ls = 0, lss = 0;
    #pragma unroll
    for (int i = 0; i < 9; i++) {
        const int idx = tid + i * 256;
        float pv = (float)(a * (double)g_dot[idx] + cst);
        pre[i] = pv;
        ls += (double)pv;
        lss += (double)pv * (double)pv;
    }
    ls = warpRedD(ls);
    lss = warpRedD(lss);
    if (lane == 0) { sred[wid] = ls; sred[8 + wid] = lss; }
    __syncthreads();
    if (tid == 0) {
        double s = 0, q = 0;
        #pragma unroll
        for (int i = 0; i < 8; i++) { s += sred[i]; q += sred[8 + i]; }
        const double lm = s / (double)NPAIR;
        const double lv = q / (double)NPAIR - lm * lm;
        bcast[1] = lm;
        bcast[2] = rsqrt(lv + EPSV);
    }
    __syncthreads();
    const float lm = (float)bcast[1];
    const float linv = (float)bcast[2];
    const float lg = lbn_gamma[0];
    const float lb = lbn_beta[0];

    #pragma unroll
    for (int i = 0; i < 9; i++) {
        const int idx = tid + i * 256;
        float z = lg * (pre[i] - lm) * linv + lb;
        out[idx] = 1.0f / (1.0f + expf(-z));
    }
}

extern "C" void kernel_launch(void* const* d_in, const int* in_sizes, int n_in,
                              void* d_out, int out_size) {
    const float* prob      = (const float*)d_in[0];
    const float* gal       = (const float*)d_in[1];
    const float* bn_gamma  = (const float*)d_in[2];
    const float* bn_beta   = (const float*)d_in[3];
    const float* fc_w      = (const float*)d_in[4];
    const float* fc_b      = (const float*)d_in[5];
    const float* lbn_gamma = (const float*)d_in[6];
    const float* lbn_beta  = (const float*)d_in[7];
    float* out = (float*)d_out;

    const int smemBytes = (2 * CC * HWX + 256 * 16 + 16 * HWX) * (int)sizeof(float); // 160 KB
    cudaFuncSetAttribute(pair_kernel, cudaFuncAttributeMaxDynamicSharedMemorySize, smemBytes);

    zero_kernel<<<1, 1>>>();
    pair_kernel<<<NPAIR, 256, smemBytes>>>(prob, gal, fc_w);
    finalize_kernel<<<1, 256>>>(bn_gamma, bn_beta, fc_w, fc_b, lbn_gamma, lbn_beta, out);
}

// round 7
// speedup vs baseline: 2.7621x; 2.7621x over previous
#include <cuda_runtime.h>
#include <cuda_bf16.h>
#include <math.h>
#include <stdint.h>

#define HWX 256
#define CC 64
#define GG 48
#define NPAIR (48*48)
#define EPSV 1e-5

// ---------------- global scratch (no allocations allowed) ----------------
__device__ double g_sum_d;
__device__ double g_sumsq_d;
__device__ float  g_dot[NPAIR];

__global__ void zero_kernel() {
    g_sum_d = 0.0;
    g_sumsq_d = 0.0;
}

__device__ __forceinline__ double warpRedD(double v) {
    #pragma unroll
    for (int o = 16; o > 0; o >>= 1)
        v += __shfl_xor_sync(0xffffffffu, v, o);
    return v;
}

__device__ __forceinline__ uint32_t smem_u32(const void* p) {
    uint32_t a;
    asm("{ .reg .u64 t; cvta.to.shared.u64 t, %1; cvt.u32.u64 %0, t; }" : "=r"(a) : "l"(p));
    return a;
}

// ldmatrix x4 transposed (b16) — baseline PTX, works on sm_103 (non-'a')
#define LDSM4T(r, addr) \
    asm volatile("ldmatrix.sync.aligned.m8n8.x4.trans.shared.b16 {%0,%1,%2,%3}, [%4];" \
        : "=r"((r)[0]), "=r"((r)[1]), "=r"((r)[2]), "=r"((r)[3]) : "r"(addr))

// mma.sync m16n8k16 bf16 -> f32 accum — baseline PTX
#define MMA16816(d, a, b0v, b1v) \
    asm volatile("mma.sync.aligned.m16n8k16.row.col.f32.bf16.bf16.f32 " \
        "{%0,%1,%2,%3}, {%4,%5,%6,%7}, {%8,%9}, {%0,%1,%2,%3};" \
        : "+f"((d)[0]), "+f"((d)[1]), "+f"((d)[2]), "+f"((d)[3]) \
        : "r"((a)[0]), "r"((a)[1]), "r"((a)[2]), "r"((a)[3]), "r"(b0v), "r"(b1v))

__device__ __forceinline__ uint32_t swap16(uint32_t x) {
    uint32_t d;
    asm("prmt.b32 %0, %1, %1, 0x1032;" : "=r"(d) : "r"(x));
    return d;
}

// ---------------- SMEM layout (offsets from 1024-aligned base) ----------------
// Operands: [128 k-rows][256 cols bf16] = 512B pitch, 16B-chunk XOR swizzle.
#define SM_A     0         // 64 KB  gal  (cols = r)
#define SM_B     65536     // 64 KB  prob (cols = s)
#define SM_M2    131072    // 256*17*4 = 17408   m2[r][hc] (pitch 17)
#define SM_M1    148480    // 16*256*4 = 16384   m1[hr][s]
#define SM_TOTAL 164864
#define SM_DYN   (SM_TOTAL + 1024)

// byte offset of element (k-row, col m): chunk = m>>3 XOR (k&7)
__device__ __forceinline__ uint32_t soff(int k, int m) {
    return ((uint32_t)k << 9) + (uint32_t)(((((m >> 3)) ^ (k & 7)) << 4) + ((m & 7) << 1));
}

// hi = truncated bf16, lo = rn-bf16 of remainder; store 4 cols at (k_hi,k_lo) rows
__device__ __forceinline__ void split_store(char* dst_hi, char* dst_lo, float4 v) {
    uint32_t ux = __float_as_uint(v.x), uy = __float_as_uint(v.y);
    uint32_t uz = __float_as_uint(v.z), uw = __float_as_uint(v.w);
    uint32_t h01, h23;
    asm("prmt.b32 %0, %1, %2, 0x7632;" : "=r"(h01) : "r"(ux), "r"(uy));
    asm("prmt.b32 %0, %1, %2, 0x7632;" : "=r"(h23) : "r"(uz), "r"(uw));
    float lx = v.x - __uint_as_float(ux & 0xffff0000u);
    float ly = v.y - __uint_as_float(uy & 0xffff0000u);
    float lz = v.z - __uint_as_float(uz & 0xffff0000u);
    float lw = v.w - __uint_as_float(uw & 0xffff0000u);
    uint32_t l01, l23;
    asm("cvt.rn.bf16x2.f32 %0, %1, %2;" : "=r"(l01) : "f"(ly), "f"(lx));
    asm("cvt.rn.bf16x2.f32 %0, %1, %2;" : "=r"(l23) : "f"(lw), "f"(lz));
    *(uint2*)dst_hi = make_uint2(h01, h23);
    *(uint2*)dst_lo = make_uint2(l01, l23);
}

// ---------------- pair kernel: one CTA per (p,g), 8 warps ----------------
// C[r,s] = sum_c gal[ig][c][r] * prob[ip][c][s]; hi/lo split, 2-pass mma.
__global__ __launch_bounds__(256)
void pair_kernel(const float* __restrict__ prob, const float* __restrict__ gal,
                 const float* __restrict__ fc_w) {
    extern __shared__ char raw[];
    const uint32_t rawaddr = smem_u32(raw);
    const uint32_t base = (rawaddr + 1023u) & ~1023u;
    char* sm = raw + (base - rawaddr);

    float* m2 = (float*)(sm + SM_M2);
    float* m1 = (float*)(sm + SM_M1);
    __shared__ double sred[24];

    const int blk = blockIdx.x;
    const int ip = blk / GG;
    const int ig = blk % GG;
    const int tid = threadIdx.x;
    const int wid = tid >> 5;
    const int lane = tid & 31;
    const int tq = lane & 3;
    const int qid = lane >> 2;

    // ---- stage + hi/lo split into [k][col] swizzled SMEM ----
    {
        const float4* gsrc = (const float4*)(gal + (size_t)ig * CC * HWX);
        const float4* psrc = (const float4*)(prob + (size_t)ip * CC * HWX);
        #pragma unroll
        for (int i = 0; i < 16; i++) {
            const int idx = tid + i * 256;      // 4096 float4: c = idx>>6, r = (idx&63)*4
            const int c = idx >> 6;
            const int r = (idx & 63) << 2;
            const uint32_t ohi = soff(2 * c, r);
            const uint32_t olo = soff(2 * c + 1, r);
            split_store(sm + SM_A + ohi, sm + SM_A + olo, gsrc[idx]);
            split_store(sm + SM_B + ohi, sm + SM_B + olo, psrc[idx]);
        }
    }
    __syncthreads();

    // ---- per-warp GEMM: rows rstrip..rstrip+31, all 256 cols in 8 chunks ----
    const int rstrip = wid * 32;
    const int g = lane >> 3;
    const int l7 = lane & 7;
    const uint32_t baseA = base + SM_A;
    const uint32_t baseB = base + SM_B;

    // A fragments, loaded once: af[i][kk][4]  (m-tile i, k-step kk)
    uint32_t af[2][8][4];
    {
        const int kA = ((g & 2) << 2) + l7;               // + 16*kk
        #pragma unroll
        for (int i = 0; i < 2; i++) {
            const int chunkA = 4 * wid + 2 * i + (g & 1);
            const uint32_t colA = (uint32_t)((chunkA ^ l7) << 4);
            #pragma unroll
            for (int kk = 0; kk < 8; kk++) {
                uint32_t addr = baseA + (uint32_t)((16 * kk + kA) << 9) + colA;
                LDSM4T(af[i][kk], addr);
            }
        }
    }

    const int kB = ((g & 1) << 3) + l7;                   // + 16*kk
    const int ng = (g & 2) >> 1;                          // chunk offset for n-tiles

    for (int n_c = 0; n_c < 8; n_c++) {
        float acc[2][4][4];
        #pragma unroll
        for (int i = 0; i < 2; i++)
            #pragma unroll
            for (int j = 0; j < 4; j++)
                #pragma unroll
                for (int q = 0; q < 4; q++) acc[i][j][q] = 0.0f;

        #pragma unroll
        for (int kk = 0; kk < 8; kk++) {
            uint32_t b01[4], b23[4];
            const uint32_t krow = (uint32_t)((16 * kk + kB) << 9);
            uint32_t a0 = baseB + krow + (uint32_t)(((4 * n_c + 0 + ng) ^ l7) << 4);
            uint32_t a1 = baseB + krow + (uint32_t)(((4 * n_c + 2 + ng) ^ l7) << 4);
            LDSM4T(b01, a0);
            LDSM4T(b23, a1);

            // pass 1: ah*bh + al*bl
            #pragma unroll
            for (int i = 0; i < 2; i++) {
                MMA16816(acc[i][0], af[i][kk], b01[0], b01[1]);
                MMA16816(acc[i][1], af[i][kk], b01[2], b01[3]);
                MMA16816(acc[i][2], af[i][kk], b23[0], b23[1]);
                MMA16816(acc[i][3], af[i][kk], b23[2], b23[3]);
            }
            // pass 2: swap bf16 halves of B -> ah*bl + al*bh
            uint32_t s01[4], s23[4];
            #pragma unroll
            for (int q = 0; q < 4; q++) { s01[q] = swap16(b01[q]); s23[q] = swap16(b23[q]); }
            #pragma unroll
            for (int i = 0; i < 2; i++) {
                MMA16816(acc[i][0], af[i][kk], s01[0], s01[1]);
                MMA16816(acc[i][1], af[i][kk], s01[2], s01[3]);
                MMA16816(acc[i][2], af[i][kk], s23[0], s23[1]);
                MMA16816(acc[i][3], af[i][kk], s23[2], s23[3]);
            }
        }

        // ---- fold this 32x32 tile into pooled maxes ----
        // D frag: c0,c1 -> row qid, cols 2tq,2tq+1; c2,c3 -> row qid+8
        #pragma unroll
        for (int i = 0; i < 2; i++) {
            // m2: per-row max over each 16-col group (n-tiles {2gg,2gg+1})
            #pragma unroll
            for (int gg = 0; gg < 2; gg++) {
                float rm0 = fmaxf(fmaxf(acc[i][2*gg][0], acc[i][2*gg][1]),
                                  fmaxf(acc[i][2*gg+1][0], acc[i][2*gg+1][1]));
                float rm1 = fmaxf(fmaxf(acc[i][2*gg][2], acc[i][2*gg][3]),
                                  fmaxf(acc[i][2*gg+1][2], acc[i][2*gg+1][3]));
                rm0 = fmaxf(rm0, __shfl_xor_sync(0xffffffffu, rm0, 1));
                rm0 = fmaxf(rm0, __shfl_xor_sync(0xffffffffu, rm0, 2));
                rm1 = fmaxf(rm1, __shfl_xor_sync(0xffffffffu, rm1, 1));
                rm1 = fmaxf(rm1, __shfl_xor_sync(0xffffffffu, rm1, 2));
                if (tq == 0) {
                    const int hc = n_c * 2 + gg;
                    m2[(rstrip + 16 * i + qid) * 17 + hc] = rm0;
                    m2[(rstrip + 16 * i + qid + 8) * 17 + hc] = rm1;
                }
            }
            // m1: per-col max over this 16-row group (hr = 2*wid + i)
            #pragma unroll
            for (int j = 0; j < 4; j++) {
                float cm0 = fmaxf(acc[i][j][0], acc[i][j][2]);
                float cm1 = fmaxf(acc[i][j][1], acc[i][j][3]);
                cm0 = fmaxf(cm0, __shfl_xor_sync(0xffffffffu, cm0, 4));
                cm0 = fmaxf(cm0, __shfl_xor_sync(0xffffffffu, cm0, 8));
                cm0 = fmaxf(cm0, __shfl_xor_sync(0xffffffffu, cm0, 16));
                cm1 = fmaxf(cm1, __shfl_xor_sync(0xffffffffu, cm1, 4));
                cm1 = fmaxf(cm1, __shfl_xor_sync(0xffffffffu, cm1, 8));
                cm1 = fmaxf(cm1, __shfl_xor_sync(0xffffffffu, cm1, 16));
                if (lane < 4) {
                    const int s = n_c * 32 + 8 * j + 2 * tq;
                    m1[(2 * wid + i) * 256 + s] = cm0;
                    m1[(2 * wid + i) * 256 + s + 1] = cm1;
                }
            }
        }
    }
    __syncthreads();

    // ---- windowed max (u = clamp(hb-2,0,12)), fc dot, global stats ----
    const int hb = tid >> 4;
    const int u = min(max(hb - 2, 0), 12);

    float s2v = -3.4e38f;                          // r = tid
    #pragma unroll
    for (int t = 0; t < 4; t++) s2v = fmaxf(s2v, m2[tid * 17 + u + t]);
    float s1v = -3.4e38f;                          // s = tid
    #pragma unroll
    for (int t = 0; t < 4; t++) s1v = fmaxf(s1v, m1[(u + t) * 256 + tid]);

    const float wv = fc_w[tid];
    double dsum = (double)s1v + (double)s2v;
    double dsq  = (double)s1v * s1v + (double)s2v * s2v;
    double ddot = (double)wv * ((double)s1v + (double)s2v);

    dsum = warpRedD(dsum);
    dsq  = warpRedD(dsq);
    ddot = warpRedD(ddot);

    if (lane == 0) {
        sred[wid] = dsum;
        sred[8 + wid] = dsq;
        sred[16 + wid] = ddot;
    }
    __syncthreads();
    if (tid == 0) {
        double s = 0, q = 0, d = 0;
        #pragma unroll
        for (int i = 0; i < 8; i++) { s += sred[i]; q += sred[8 + i]; d += sred[16 + i]; }
        atomicAdd(&g_sum_d, s);
        atomicAdd(&g_sumsq_d, q);
        g_dot[blk] = (float)d;
    }
}

// ---------------- finalize: BN -> fc -> pair-sum -> lbn -> sigmoid ----------------
__global__ __launch_bounds__(256)
void finalize_kernel(const float* __restrict__ bn_gamma, const float* __restrict__ bn_beta,
                     const float* __restrict__ fc_w, const float* __restrict__ fc_b,
                     const float* __restrict__ lbn_gamma, const float* __restrict__ lbn_beta,
                     float* __restrict__ out) {
    __shared__ double sred[24];
    __shared__ double bcast[4];
    const int tid = threadIdx.x;
    const int wid = tid >> 5, lane = tid & 31;

    double wv = (double)fc_w[tid];
    wv = warpRedD(wv);
    if (lane == 0) sred[wid] = wv;
    __syncthreads();
    if (tid == 0) {
        double s = 0;
        #pragma unroll
        for (int i = 0; i < 8; i++) s += sred[i];
        bcast[0] = s;
    }
    __syncthreads();
    const double Wsum = bcast[0];

    const double N1 = 2.0 * (double)NPAIR * (double)HWX;
    const double m = g_sum_d / N1;
    const double v = g_sumsq_d / N1 - m * m;
    const double a = (double)bn_gamma[0] * rsqrt(v + EPSV);
    const double cst = 2.0 * (-a * m * Wsum + (double)bn_beta[0] * Wsum + (double)fc_b[0]);

    float pre[9];
    double ls = 0, lss = 0;
    #pragma unroll
    for (int i = 0; i < 9; i++) {
        const int idx = tid + i * 256;
        float pv = (float)(a * (double)g_dot[idx] + cst);
        pre[i] = pv;
        ls += (double)pv;
        lss += (double)pv * (double)pv;
    }
    ls = warpRedD(ls);
    lss = warpRedD(lss);
    if (lane == 0) { sred[wid] = ls; sred[8 + wid] = lss; }
    __syncthreads();
    if (tid == 0) {
        double s = 0, q = 0;
        #pragma unroll
        for (int i = 0; i < 8; i++) { s += sred[i]; q += sred[8 + i]; }
        const double lm = s / (double)NPAIR;
        const double lv = q / (double)NPAIR - lm * lm;
        bcast[1] = lm;
        bcast[2] = rsqrt(lv + EPSV);
    }
    __syncthreads();
    const float lm = (float)bcast[1];
    const float linv = (float)bcast[2];
    const float lg = lbn_gamma[0];
    const float lb = lbn_beta[0];

    #pragma unroll
    for (int i = 0; i < 9; i++) {
        const int idx = tid + i * 256;
        float z = lg * (pre[i] - lm) * linv + lb;
        out[idx] = 1.0f / (1.0f + expf(-z));
    }
}

extern "C" void kernel_launch(void* const* d_in, const int* in_sizes, int n_in,
                              void* d_out, int out_size) {
    const float* prob      = (const float*)d_in[0];
    const float* gal       = (const float*)d_in[1];
    const float* bn_gamma  = (const float*)d_in[2];
    const float* bn_beta   = (const float*)d_in[3];
    const float* fc_w      = (const float*)d_in[4];
    const float* fc_b      = (const float*)d_in[5];
    const float* lbn_gamma = (const float*)d_in[6];
    const float* lbn_beta  = (const float*)d_in[7];
    float* out = (float*)d_out;

    cudaFuncSetAttribute(pair_kernel, cudaFuncAttributeMaxDynamicSharedMemorySize, SM_DYN);

    zero_kernel<<<1, 1>>>();
    pair_kernel<<<NPAIR, 256, SM_DYN>>>(prob, gal, fc_w);
    finalize_kernel<<<1, 256>>>(bn_gamma, bn_beta, fc_w, fc_b, lbn_gamma, lbn_beta, out);
}

// round 9
// speedup vs baseline: 3.2230x; 1.1669x over previous
#include <cuda_runtime.h>
#include <cuda_fp16.h>
#include <math.h>
#include <stdint.h>

#define HWX 256
#define CC 64
#define GG 48
#define NPAIR (48*48)
#define EPSV 1e-5

// ---------------- global scratch (no allocations allowed) ----------------
// Statically zero-initialized; finalize_kernel resets them at the end of every
// launch so each replay (graph) sees zeros again. No zero kernel needed.
__device__ double g_sum_d = 0.0;
__device__ double g_sumsq_d = 0.0;
__device__ float  g_dot[NPAIR];

__device__ __forceinline__ double warpRedD(double v) {
    #pragma unroll
    for (int o = 16; o > 0; o >>= 1)
        v += __shfl_xor_sync(0xffffffffu, v, o);
    return v;
}

__device__ __forceinline__ uint32_t smem_u32(const void* p) {
    uint32_t a;
    asm("{ .reg .u64 t; cvta.to.shared.u64 t, %1; cvt.u32.u64 %0, t; }" : "=r"(a) : "l"(p));
    return a;
}

// ldmatrix x4 transposed (b16) — baseline PTX, works on sm_103 (non-'a')
#define LDSM4T(r, addr) \
    asm volatile("ldmatrix.sync.aligned.m8n8.x4.trans.shared.b16 {%0,%1,%2,%3}, [%4];" \
        : "=r"((r)[0]), "=r"((r)[1]), "=r"((r)[2]), "=r"((r)[3]) : "r"(addr))

// mma.sync m16n8k16 fp16 -> f32 accum — baseline PTX
#define MMA16816(d, a, b0v, b1v) \
    asm volatile("mma.sync.aligned.m16n8k16.row.col.f32.f16.f16.f32 " \
        "{%0,%1,%2,%3}, {%4,%5,%6,%7}, {%8,%9}, {%0,%1,%2,%3};" \
        : "+f"((d)[0]), "+f"((d)[1]), "+f"((d)[2]), "+f"((d)[3]) \
        : "r"((a)[0]), "r"((a)[1]), "r"((a)[2]), "r"((a)[3]), "r"(b0v), "r"(b1v))

// ---------------- SMEM layout (offsets from 1024-aligned base) ----------------
// Four fp16 planes [64 k-rows][256 cols] = 512B pitch, 16B-chunk XOR swizzle.
#define SM_AH    0         // 32 KB  gal hi  (cols = r)
#define SM_AL    32768     // 32 KB  gal lo
#define SM_BH    65536     // 32 KB  prob hi (cols = s)
#define SM_BL    98304     // 32 KB  prob lo
#define SM_M2    131072    // 256*17*4 = 17408   m2[r][hc] (pitch 17)
#define SM_M1    148480    // 16*256*4 = 16384   m1[hr][s]
#define SM_TOTAL 164864
#define SM_DYN   (SM_TOTAL + 1024)

// byte offset of element (k-row, col m): chunk = m>>3 XOR (k&7)
__device__ __forceinline__ uint32_t soff(int k, int m) {
    return ((uint32_t)k << 9) + (uint32_t)(((((m >> 3)) ^ (k & 7)) << 4) + ((m & 7) << 1));
}

// hi = rn fp16, lo = rn fp16 of remainder; store 4 cols (8B each plane)
__device__ __forceinline__ void split_store_f16(char* dh, char* dl, float4 v) {
    __half2 h01 = __floats2half2_rn(v.x, v.y);   // x -> lo half, y -> hi half
    __half2 h23 = __floats2half2_rn(v.z, v.w);
    float2 f01 = __half22float2(h01);
    float2 f23 = __half22float2(h23);
    __half2 l01 = __floats2half2_rn(v.x - f01.x, v.y - f01.y);
    __half2 l23 = __floats2half2_rn(v.z - f23.x, v.w - f23.y);
    *(uint2*)dh = make_uint2(*(uint32_t*)&h01, *(uint32_t*)&h23);
    *(uint2*)dl = make_uint2(*(uint32_t*)&l01, *(uint32_t*)&l23);
}

// ---------------- pair kernel: one CTA per (p,g), 8 warps ----------------
// C[r,s] = sum_c gal[ig][c][r] * prob[ip][c][s]
// 3-term fp16 split: C = ah*bh + ah*bl + al*bh  (al*bl ~ 2^-22, dropped)
__global__ __launch_bounds__(256)
void pair_kernel(const float* __restrict__ prob, const float* __restrict__ gal,
                 const float* __restrict__ fc_w) {
    extern __shared__ char raw[];
    const uint32_t rawaddr = smem_u32(raw);
    const uint32_t base = (rawaddr + 1023u) & ~1023u;
    char* sm = raw + (base - rawaddr);

    float* m2 = (float*)(sm + SM_M2);
    float* m1 = (float*)(sm + SM_M1);
    __shared__ double sred[24];

    const int blk = blockIdx.x;
    const int ip = blk / GG;
    const int ig = blk % GG;
    const int tid = threadIdx.x;
    const int wid = tid >> 5;
    const int lane = tid & 31;
    const int tq = lane & 3;
    const int qid = lane >> 2;

    // ---- stage + hi/lo split into four [k][col] swizzled planes ----
    {
        const float4* gsrc = (const float4*)(gal + (size_t)ig * CC * HWX);
        const float4* psrc = (const float4*)(prob + (size_t)ip * CC * HWX);
        #pragma unroll
        for (int i = 0; i < 16; i++) {
            const int idx = tid + i * 256;      // 4096 float4: c = idx>>6, r = (idx&63)*4
            const int c = idx >> 6;
            const int r = (idx & 63) << 2;
            const uint32_t o = soff(c, r);
            split_store_f16(sm + SM_AH + o, sm + SM_AL + o, gsrc[idx]);
            split_store_f16(sm + SM_BH + o, sm + SM_BL + o, psrc[idx]);
        }
    }
    __syncthreads();

    // ---- per-warp GEMM: rows rstrip..rstrip+31, all 256 cols in 8 chunks ----
    const int rstrip = wid * 32;
    const int g = lane >> 3;
    const int l7 = lane & 7;
    const uint32_t baseAH = base + SM_AH;
    const uint32_t baseAL = base + SM_AL;
    const uint32_t baseBH = base + SM_BH;
    const uint32_t baseBL = base + SM_BL;

    // A fragments, loaded once: [i][kk][4] for hi and lo (m-tile i, k-step kk)
    uint32_t afh[2][4][4], afl[2][4][4];
    {
        const int kA = ((g & 2) << 2) + l7;               // + 16*kk
        #pragma unroll
        for (int i = 0; i < 2; i++) {
            const int chunkA = 4 * wid + 2 * i + (g & 1);
            const uint32_t colA = (uint32_t)((chunkA ^ l7) << 4);
            #pragma unroll
            for (int kk = 0; kk < 4; kk++) {
                const uint32_t row = (uint32_t)((16 * kk + kA) << 9) + colA;
                LDSM4T(afh[i][kk], baseAH + row);
                LDSM4T(afl[i][kk], baseAL + row);
            }
        }
    }

    const int kB = ((g & 1) << 3) + l7;                   // + 16*kk
    const int ng = (g & 2) >> 1;                          // chunk offset for n-tiles

    #pragma unroll 2
    for (int n_c = 0; n_c < 8; n_c++) {
        float acc[2][4][4];
        #pragma unroll
        for (int i = 0; i < 2; i++)
            #pragma unroll
            for (int j = 0; j < 4; j++)
                #pragma unroll
                for (int q = 0; q < 4; q++) acc[i][j][q] = 0.0f;

        const uint32_t c01 = (uint32_t)(((4 * n_c + 0 + ng) ^ l7) << 4);
        const uint32_t c23 = (uint32_t)(((4 * n_c + 2 + ng) ^ l7) << 4);

        #pragma unroll
        for (int kk = 0; kk < 4; kk++) {
            const uint32_t krow = (uint32_t)((16 * kk + kB) << 9);
            uint32_t bh01[4], bh23[4], bl01[4], bl23[4];
            LDSM4T(bh01, baseBH + krow + c01);
            LDSM4T(bh23, baseBH + krow + c23);
            LDSM4T(bl01, baseBL + krow + c01);
            LDSM4T(bl23, baseBL + krow + c23);

            #pragma unroll
            for (int i = 0; i < 2; i++) {
                // ah * bh
                MMA16816(acc[i][0], afh[i][kk], bh01[0], bh01[1]);
                MMA16816(acc[i][1], afh[i][kk], bh01[2], bh01[3]);
                MMA16816(acc[i][2], afh[i][kk], bh23[0], bh23[1]);
                MMA16816(acc[i][3], afh[i][kk], bh23[2], bh23[3]);
                // ah * bl
                MMA16816(acc[i][0], afh[i][kk], bl01[0], bl01[1]);
                MMA16816(acc[i][1], afh[i][kk], bl01[2], bl01[3]);
                MMA16816(acc[i][2], afh[i][kk], bl23[0], bl23[1]);
                MMA16816(acc[i][3], afh[i][kk], bl23[2], bl23[3]);
                // al * bh
                MMA16816(acc[i][0], afl[i][kk], bh01[0], bh01[1]);
                MMA16816(acc[i][1], afl[i][kk], bh01[2], bh01[3]);
                MMA16816(acc[i][2], afl[i][kk], bh23[0], bh23[1]);
                MMA16816(acc[i][3], afl[i][kk], bh23[2], bh23[3]);
            }
        }

        // ---- fold this 32x32 tile into pooled maxes ----
        // D frag: c0,c1 -> row qid, cols 2tq,2tq+1; c2,c3 -> row qid+8
        #pragma unroll
        for (int i = 0; i < 2; i++) {
            // m2: per-row max over each 16-col group (n-tiles {2gg,2gg+1})
            #pragma unroll
            for (int gg = 0; gg < 2; gg++) {
                float rm0 = fmaxf(fmaxf(acc[i][2*gg][0], acc[i][2*gg][1]),
                                  fmaxf(acc[i][2*gg+1][0], acc[i][2*gg+1][1]));
                float rm1 = fmaxf(fmaxf(acc[i][2*gg][2], acc[i][2*gg][3]),
                                  fmaxf(acc[i][2*gg+1][2], acc[i][2*gg+1][3]));
                rm0 = fmaxf(rm0, __shfl_xor_sync(0xffffffffu, rm0, 1));
                rm0 = fmaxf(rm0, __shfl_xor_sync(0xffffffffu, rm0, 2));
                rm1 = fmaxf(rm1, __shfl_xor_sync(0xffffffffu, rm1, 1));
                rm1 = fmaxf(rm1, __shfl_xor_sync(0xffffffffu, rm1, 2));
                if (tq == 0) {
                    const int hc = n_c * 2 + gg;
                    m2[(rstrip + 16 * i + qid) * 17 + hc] = rm0;
                    m2[(rstrip + 16 * i + qid + 8) * 17 + hc] = rm1;
                }
            }
            // m1: per-col max over this 16-row group (hr = 2*wid + i)
            #pragma unroll
            for (int j = 0; j < 4; j++) {
                float cm0 = fmaxf(acc[i][j][0], acc[i][j][2]);
                float cm1 = fmaxf(acc[i][j][1], acc[i][j][3]);
                cm0 = fmaxf(cm0, __shfl_xor_sync(0xffffffffu, cm0, 4));
                cm0 = fmaxf(cm0, __shfl_xor_sync(0xffffffffu, cm0, 8));
                cm0 = fmaxf(cm0, __shfl_xor_sync(0xffffffffu, cm0, 16));
                cm1 = fmaxf(cm1, __shfl_xor_sync(0xffffffffu, cm1, 4));
                cm1 = fmaxf(cm1, __shfl_xor_sync(0xffffffffu, cm1, 8));
                cm1 = fmaxf(cm1, __shfl_xor_sync(0xffffffffu, cm1, 16));
                if (lane < 4) {
                    const int s = n_c * 32 + 8 * j + 2 * tq;
                    m1[(2 * wid + i) * 256 + s] = cm0;
                    m1[(2 * wid + i) * 256 + s + 1] = cm1;
                }
            }
        }
    }
    __syncthreads();

    // ---- windowed max (u = clamp(hb-2,0,12)), fc dot, global stats ----
    const int hb = tid >> 4;
    const int u = min(max(hb - 2, 0), 12);

    float s2v = -3.4e38f;                          // r = tid
    #pragma unroll
    for (int t = 0; t < 4; t++) s2v = fmaxf(s2v, m2[tid * 17 + u + t]);
    float s1v = -3.4e38f;                          // s = tid
    #pragma unroll
    for (int t = 0; t < 4; t++) s1v = fmaxf(s1v, m1[(u + t) * 256 + tid]);

    const float wv = fc_w[tid];
    double dsum = (double)s1v + (double)s2v;
    double dsq  = (double)s1v * s1v + (double)s2v * s2v;
    double ddot = (double)wv * ((double)s1v + (double)s2v);

    dsum = warpRedD(dsum);
    dsq  = warpRedD(dsq);
    ddot = warpRedD(ddot);

    if (lane == 0) {
        sred[wid] = dsum;
        sred[8 + wid] = dsq;
        sred[16 + wid] = ddot;
    }
    __syncthreads();
    if (tid == 0) {
        double s = 0, q = 0, d = 0;
        #pragma unroll
        for (int i = 0; i < 8; i++) { s += sred[i]; q += sred[8 + i]; d += sred[16 + i]; }
        atomicAdd(&g_sum_d, s);
        atomicAdd(&g_sumsq_d, q);
        g_dot[blk] = (float)d;
    }
}

// ---------------- finalize: BN -> fc -> pair-sum -> lbn -> sigmoid ----------------
__global__ __launch_bounds__(256)
void finalize_kernel(const float* __restrict__ bn_gamma, const float* __restrict__ bn_beta,
                     const float* __restrict__ fc_w, const float* __restrict__ fc_b,
                     const float* __restrict__ lbn_gamma, const float* __restrict__ lbn_beta,
                     float* __restrict__ out) {
    __shared__ double sred[24];
    __shared__ double bcast[4];
    const int tid = threadIdx.x;
    const int wid = tid >> 5, lane = tid & 31;

    double wv = (double)fc_w[tid];
    wv = warpRedD(wv);
    if (lane == 0) sred[wid] = wv;
    __syncthreads();
    if (tid == 0) {
        double s = 0;
        #pragma unroll
        for (int i = 0; i < 8; i++) s += sred[i];
        bcast[0] = s;
    }
    __syncthreads();
    const double Wsum = bcast[0];

    const double N1 = 2.0 * (double)NPAIR * (double)HWX;
    const double m = g_sum_d / N1;
    const double v = g_sumsq_d / N1 - m * m;
    const double a = (double)bn_gamma[0] * rsqrt(v + EPSV);
    const double cst = 2.0 * (-a * m * Wsum + (double)bn_beta[0] * Wsum + (double)fc_b[0]);

    float pre[9];
    double ls = 0, lss = 0;
    #pragma unroll
    for (int i = 0; i < 9; i++) {
        const int idx = tid + i * 256;
        float pv = (float)(a * (double)g_dot[idx] + cst);
        pre[i] = pv;
        ls += (double)pv;
        lss += (double)pv * (double)pv;
    }
    ls = warpRedD(ls);
    lss = warpRedD(lss);
    if (lane == 0) { sred[wid] = ls; sred[8 + wid] = lss; }
    __syncthreads();
    if (tid == 0) {
        double s = 0, q = 0;
        #pragma unroll
        for (int i = 0; i < 8; i++) { s += sred[i]; q += sred[8 + i]; }
        const double lm = s / (double)NPAIR;
        const double lv = q / (double)NPAIR - lm * lm;
        bcast[1] = lm;
        bcast[2] = rsqrt(lv + EPSV);
        // reset global accumulators for the next (graph-replayed) launch
        g_sum_d = 0.0;
        g_sumsq_d = 0.0;
    }
    __syncthreads();
    const float lm = (float)bcast[1];
    const float linv = (float)bcast[2];
    const float lg = lbn_gamma[0];
    const float lb = lbn_beta[0];

    #pragma unroll
    for (int i = 0; i < 9; i++) {
        const int idx = tid + i * 256;
        float z = lg * (pre[i] - lm) * linv + lb;
        out[idx] = 1.0f / (1.0f + expf(-z));
    }
}

extern "C" void kernel_launch(void* const* d_in, const int* in_sizes, int n_in,
                              void* d_out, int out_size) {
    const float* prob      = (const float*)d_in[0];
    const float* gal       = (const float*)d_in[1];
    const float* bn_gamma  = (const float*)d_in[2];
    const float* bn_beta   = (const float*)d_in[3];
    const float* fc_w      = (const float*)d_in[4];
    const float* fc_b      = (const float*)d_in[5];
    const float* lbn_gamma = (const float*)d_in[6];
    const float* lbn_beta  = (const float*)d_in[7];
    float* out = (float*)d_out;

    cudaFuncSetAttribute(pair_kernel, cudaFuncAttributeMaxDynamicSharedMemorySize, SM_DYN);

    pair_kernel<<<NPAIR, 256, SM_DYN>>>(prob, gal, fc_w);
    finalize_kernel<<<1, 256>>>(bn_gamma, bn_beta, fc_w, fc_b, lbn_gamma, lbn_beta, out);
}

// round 11
// speedup vs baseline: 3.3822x; 1.0494x over previous
#include <cuda_runtime.h>
#include <cuda_fp16.h>
#include <math.h>
#include <stdint.h>

#define HWX 256
#define CC 64
#define GG 48
#define NPAIR (48*48)
#define EPSV 1e-5

// ---------------- global scratch (no allocations allowed) ----------------
// Statically zeroed; the last CTA resets them after use so every graph replay
// sees zeros again (deterministic).
__device__ double g_sum_d = 0.0;
__device__ double g_sumsq_d = 0.0;
__device__ unsigned int g_count = 0;
__device__ float  g_dot[NPAIR];

__device__ __forceinline__ double warpRedD(double v) {
    #pragma unroll
    for (int o = 16; o > 0; o >>= 1)
        v += __shfl_xor_sync(0xffffffffu, v, o);
    return v;
}

__device__ __forceinline__ uint32_t smem_u32(const void* p) {
    uint32_t a;
    asm("{ .reg .u64 t; cvta.to.shared.u64 t, %1; cvt.u32.u64 %0, t; }" : "=r"(a) : "l"(p));
    return a;
}

// ldmatrix x4 transposed (b16) — baseline PTX, works on sm_103 (non-'a')
#define LDSM4T(r, addr) \
    asm volatile("ldmatrix.sync.aligned.m8n8.x4.trans.shared.b16 {%0,%1,%2,%3}, [%4];" \
        : "=r"((r)[0]), "=r"((r)[1]), "=r"((r)[2]), "=r"((r)[3]) : "r"(addr))

// mma.sync m16n8k16 fp16 -> f32 accum — baseline PTX
#define MMA16816(d, a, b0v, b1v) \
    asm volatile("mma.sync.aligned.m16n8k16.row.col.f32.f16.f16.f32 " \
        "{%0,%1,%2,%3}, {%4,%5,%6,%7}, {%8,%9}, {%0,%1,%2,%3};" \
        : "+f"((d)[0]), "+f"((d)[1]), "+f"((d)[2]), "+f"((d)[3]) \
        : "r"((a)[0]), "r"((a)[1]), "r"((a)[2]), "r"((a)[3]), "r"(b0v), "r"(b1v))

// ---------------- SMEM layout (offsets from 1024-aligned base) ----------------
// Four fp16 planes [64 k-rows][256 cols] = 512B pitch, 16B-chunk XOR swizzle.
#define SM_AH    0         // 32 KB  gal hi  (cols = r)
#define SM_AL    32768     // 32 KB  gal lo
#define SM_BH    65536     // 32 KB  prob hi (cols = s)
#define SM_BL    98304     // 32 KB  prob lo
#define SM_M2    131072    // 256*17*4 = 17408   m2[r][hc] (pitch 17)
#define SM_M1    148480    // 16*256*4 = 16384   m1[hr][s]
#define SM_TOTAL 164864
#define SM_DYN   (SM_TOTAL + 1024)

// byte offset of element (k-row, col m): chunk = m>>3 XOR (k&7)
__device__ __forceinline__ uint32_t soff(int k, int m) {
    return ((uint32_t)k << 9) + (uint32_t)(((((m >> 3)) ^ (k & 7)) << 4) + ((m & 7) << 1));
}

// hi = rn fp16, lo = rn fp16 of remainder; store 4 cols (8B each plane)
__device__ __forceinline__ void split_store_f16(char* dh, char* dl, float4 v) {
    __half2 h01 = __floats2half2_rn(v.x, v.y);
    __half2 h23 = __floats2half2_rn(v.z, v.w);
    float2 f01 = __half22float2(h01);
    float2 f23 = __half22float2(h23);
    __half2 l01 = __floats2half2_rn(v.x - f01.x, v.y - f01.y);
    __half2 l23 = __floats2half2_rn(v.z - f23.x, v.w - f23.y);
    *(uint2*)dh = make_uint2(*(uint32_t*)&h01, *(uint32_t*)&h23);
    *(uint2*)dl = make_uint2(*(uint32_t*)&l01, *(uint32_t*)&l23);
}

// ---------------- fused kernel: one CTA per (p,g), 16 warps ----------------
// C[r,s] = sum_c gal[ig][c][r] * prob[ip][c][s]
// 3-term fp16 split: C = ah*bh + ah*bl + al*bh  (al*bl ~ 2^-22, dropped)
// Last CTA to finish runs the finalize (BN -> fc -> pair-sum -> lbn -> sigmoid).
__global__ __launch_bounds__(512)
void pair_kernel(const float* __restrict__ prob, const float* __restrict__ gal,
                 const float* __restrict__ bn_gamma, const float* __restrict__ bn_beta,
                 const float* __restrict__ fc_w, const float* __restrict__ fc_b,
                 const float* __restrict__ lbn_gamma, const float* __restrict__ lbn_beta,
                 float* __restrict__ out) {
    extern __shared__ char raw[];
    const uint32_t rawaddr = smem_u32(raw);
    const uint32_t base = (rawaddr + 1023u) & ~1023u;
    char* sm = raw + (base - rawaddr);

    float* m2 = (float*)(sm + SM_M2);
    float* m1 = (float*)(sm + SM_M1);
    __shared__ double sred[24];
    __shared__ double bcast[4];
    __shared__ int sLast;

    const int blk = blockIdx.x;
    const int ip = blk / GG;
    const int ig = blk % GG;
    const int tid = threadIdx.x;
    const int wid = tid >> 5;
    const int lane = tid & 31;
    const int tq = lane & 3;
    const int qid = lane >> 2;

    // ---- stage + hi/lo split into four [k][col] swizzled planes ----
    {
        const float4* gsrc = (const float4*)(gal + (size_t)ig * CC * HWX);
        const float4* psrc = (const float4*)(prob + (size_t)ip * CC * HWX);
        #pragma unroll
        for (int i = 0; i < 8; i++) {
            const int idx = tid + i * 512;      // 4096 float4: c = idx>>6, r = (idx&63)*4
            const int c = idx >> 6;
            const int r = (idx & 63) << 2;
            const uint32_t o = soff(c, r);
            split_store_f16(sm + SM_AH + o, sm + SM_AL + o, gsrc[idx]);
            split_store_f16(sm + SM_BH + o, sm + SM_BL + o, psrc[idx]);
        }
    }
    __syncthreads();

    // ---- per-warp GEMM: rows rstrip..rstrip+15 (one m16 tile), 8 col chunks ----
    const int rstrip = wid * 16;
    const int g = lane >> 3;
    const int l7 = lane & 7;
    const uint32_t baseAH = base + SM_AH;
    const uint32_t baseAL = base + SM_AL;
    const uint32_t baseBH = base + SM_BH;
    const uint32_t baseBL = base + SM_BL;

    // A fragments, loaded once: [kk][4] for hi and lo
    uint32_t afh[4][4], afl[4][4];
    {
        const int kA = ((g & 2) << 2) + l7;               // + 16*kk
        const int chunkA = 2 * wid + (g & 1);
        const uint32_t colA = (uint32_t)((chunkA ^ l7) << 4);
        #pragma unroll
        for (int kk = 0; kk < 4; kk++) {
            const uint32_t row = (uint32_t)((16 * kk + kA) << 9) + colA;
            LDSM4T(afh[kk], baseAH + row);
            LDSM4T(afl[kk], baseAL + row);
        }
    }

    const int kB = ((g & 1) << 3) + l7;                   // + 16*kk
    const int ng = (g & 2) >> 1;                          // chunk offset for n-tiles

    #pragma unroll 2
    for (int n_c = 0; n_c < 8; n_c++) {
        float acc[4][4];
        #pragma unroll
        for (int j = 0; j < 4; j++)
            #pragma unroll
            for (int q = 0; q < 4; q++) acc[j][q] = 0.0f;

        const uint32_t c01 = (uint32_t)(((4 * n_c + 0 + ng) ^ l7) << 4);
        const uint32_t c23 = (uint32_t)(((4 * n_c + 2 + ng) ^ l7) << 4);

        #pragma unroll
        for (int kk = 0; kk < 4; kk++) {
            const uint32_t krow = (uint32_t)((16 * kk + kB) << 9);
            uint32_t bh01[4], bh23[4], bl01[4], bl23[4];
            LDSM4T(bh01, baseBH + krow + c01);
            LDSM4T(bh23, baseBH + krow + c23);
            LDSM4T(bl01, baseBL + krow + c01);
            LDSM4T(bl23, baseBL + krow + c23);

            // ah * bh
            MMA16816(acc[0], afh[kk], bh01[0], bh01[1]);
            MMA16816(acc[1], afh[kk], bh01[2], bh01[3]);
            MMA16816(acc[2], afh[kk], bh23[0], bh23[1]);
            MMA16816(acc[3], afh[kk], bh23[2], bh23[3]);
            // ah * bl
            MMA16816(acc[0], afh[kk], bl01[0], bl01[1]);
            MMA16816(acc[1], afh[kk], bl01[2], bl01[3]);
            MMA16816(acc[2], afh[kk], bl23[0], bl23[1]);
            MMA16816(acc[3], afh[kk], bl23[2], bl23[3]);
            // al * bh
            MMA16816(acc[0], afl[kk], bh01[0], bh01[1]);
            MMA16816(acc[1], afl[kk], bh01[2], bh01[3]);
            MMA16816(acc[2], afl[kk], bh23[0], bh23[1]);
            MMA16816(acc[3], afl[kk], bh23[2], bh23[3]);
        }

        // ---- fold this 16x32 tile into pooled maxes ----
        // D frag: c0,c1 -> row qid, cols 2tq,2tq+1; c2,c3 -> row qid+8
        // m2: per-row max over each 16-col group (n-tiles {2gg,2gg+1})
        #pragma unroll
        for (int gg = 0; gg < 2; gg++) {
            float rm0 = fmaxf(fmaxf(acc[2*gg][0], acc[2*gg][1]),
                              fmaxf(acc[2*gg+1][0], acc[2*gg+1][1]));
            float rm1 = fmaxf(fmaxf(acc[2*gg][2], acc[2*gg][3]),
                              fmaxf(acc[2*gg+1][2], acc[2*gg+1][3]));
            rm0 = fmaxf(rm0, __shfl_xor_sync(0xffffffffu, rm0, 1));
            rm0 = fmaxf(rm0, __shfl_xor_sync(0xffffffffu, rm0, 2));
            rm1 = fmaxf(rm1, __shfl_xor_sync(0xffffffffu, rm1, 1));
            rm1 = fmaxf(rm1, __shfl_xor_sync(0xffffffffu, rm1, 2));
            if (tq == 0) {
                const int hc = n_c * 2 + gg;
                m2[(rstrip + qid) * 17 + hc] = rm0;
                m2[(rstrip + qid + 8) * 17 + hc] = rm1;
            }
        }
        // m1: per-col max over this warp's 16-row group (hr = wid)
        #pragma unroll
        for (int j = 0; j < 4; j++) {
            float cm0 = fmaxf(acc[j][0], acc[j][2]);
            float cm1 = fmaxf(acc[j][1], acc[j][3]);
            cm0 = fmaxf(cm0, __shfl_xor_sync(0xffffffffu, cm0, 4));
            cm0 = fmaxf(cm0, __shfl_xor_sync(0xffffffffu, cm0, 8));
            cm0 = fmaxf(cm0, __shfl_xor_sync(0xffffffffu, cm0, 16));
            cm1 = fmaxf(cm1, __shfl_xor_sync(0xffffffffu, cm1, 4));
            cm1 = fmaxf(cm1, __shfl_xor_sync(0xffffffffu, cm1, 8));
            cm1 = fmaxf(cm1, __shfl_xor_sync(0xffffffffu, cm1, 16));
            if (lane < 4) {
                const int s = n_c * 32 + 8 * j + 2 * tq;
                m1[wid * 256 + s] = cm0;
                m1[wid * 256 + s + 1] = cm1;
            }
        }
    }
    __syncthreads();

    // ---- windowed max (u = clamp(hb-2,0,12)), fc dot, global stats ----
    // Only threads 0..255 carry the 256 r/s positions.
    if (tid < 256) {
        const int hb = tid >> 4;
        const int u = min(max(hb - 2, 0), 12);

        float s2v = -3.4e38f;                          // r = tid
        #pragma unroll
        for (int t = 0; t < 4; t++) s2v = fmaxf(s2v, m2[tid * 17 + u + t]);
        float s1v = -3.4e38f;                          // s = tid
        #pragma unroll
        for (int t = 0; t < 4; t++) s1v = fmaxf(s1v, m1[(u + t) * 256 + tid]);

        const float wv = fc_w[tid];
        double dsum = (double)s1v + (double)s2v;
        double dsq  = (double)s1v * s1v + (double)s2v * s2v;
        double ddot = (double)wv * ((double)s1v + (double)s2v);

        dsum = warpRedD(dsum);
        dsq  = warpRedD(dsq);
        ddot = warpRedD(ddot);

        if (lane == 0) {
            sred[wid] = dsum;
            sred[8 + wid] = dsq;
            sred[16 + wid] = ddot;
        }
    }
    __syncthreads();
    if (tid == 0) {
        double s = 0, q = 0, d = 0;
        #pragma unroll
        for (int i = 0; i < 8; i++) { s += sred[i]; q += sred[8 + i]; d += sred[16 + i]; }
        atomicAdd(&g_sum_d, s);
        atomicAdd(&g_sumsq_d, q);
        g_dot[blk] = d;
        __threadfence();
        unsigned int old = atomicAdd(&g_count, 1u);
        sLast = (old == NPAIR - 1) ? 1 : 0;
    }
    __syncthreads();

    if (sLast) {
        // ================= fused finalize (last CTA only) =================
        // Wsum
        double wv = (tid < 256) ? (double)fc_w[tid] : 0.0;
        if (tid < 256) {
            wv = warpRedD(wv);
            if (lane == 0) sred[wid] = wv;
        }
        __syncthreads();
        if (tid == 0) {
            double s = 0;
            #pragma unroll
            for (int i = 0; i < 8; i++) s += sred[i];
            const double Wsum = s;
            // read stats through L2 (atomic read: other CTAs wrote via atomics)
            const double gs = atomicAdd(&g_sum_d, 0.0);
            const double gq = atomicAdd(&g_sumsq_d, 0.0);
            const double N1 = 2.0 * (double)NPAIR * (double)HWX;
            const double m = gs / N1;
            const double v = gq / N1 - m * m;
            const double a = (double)bn_gamma[0] * rsqrt(v + EPSV);
            bcast[0] = a;
            bcast[1] = 2.0 * (-a * m * Wsum + (double)bn_beta[0] * Wsum + (double)fc_b[0]);
            // reset for next (graph-replayed) launch
            g_sum_d = 0.0;
            g_sumsq_d = 0.0;
            g_count = 0u;
        }
        __syncthreads();
        const double a = bcast[0];
        const double cst = bcast[1];

        float pre[9];
        double ls = 0, lss = 0;
        if (tid < 256) {
            #pragma unroll
            for (int i = 0; i < 9; i++) {
                const int idx = tid + i * 256;
                float dv = __ldcg(&g_dot[idx]);     // bypass stale L1
                float pv = (float)(a * (double)dv + cst);
                pre[i] = pv;
                ls += (double)pv;
                lss += (double)pv * (double)pv;
            }
            ls = warpRedD(ls);
            lss = warpRedD(lss);
            if (lane == 0) { sred[wid] = ls; sred[8 + wid] = lss; }
        }
        __syncthreads();
        if (tid == 0) {
            double s = 0, q = 0;
            #pragma unroll
            for (int i = 0; i < 8; i++) { s += sred[i]; q += sred[8 + i]; }
            const double lm = s / (double)NPAIR;
            const double lv = q / (double)NPAIR - lm * lm;
            bcast[2] = lm;
            bcast[3] = rsqrt(lv + EPSV);
        }
        __syncthreads();
        const float lm = (float)bcast[2];
        const float linv = (float)bcast[3];
        const float lg = lbn_gamma[0];
        const float lb = lbn_beta[0];

        if (tid < 256) {
            #pragma unroll
            for (int i = 0; i < 9; i++) {
                const int idx = tid + i * 256;
                float z = lg * (pre[i] - lm) * linv + lb;
                out[idx] = 1.0f / (1.0f + expf(-z));
            }
        }
    }
}

extern "C" void kernel_launch(void* const* d_in, const int* in_sizes, int n_in,
                              void* d_out, int out_size) {
    const float* prob      = (const float*)d_in[0];
    const float* gal       = (const float*)d_in[1];
    const float* bn_gamma  = (const float*)d_in[2];
    const float* bn_beta   = (const float*)d_in[3];
    const float* fc_w      = (const float*)d_in[4];
    const float* fc_b      = (const float*)d_in[5];
    const float* lbn_gamma = (const float*)d_in[6];
    const float* lbn_beta  = (const float*)d_in[7];
    float* out = (float*)d_out;

    cudaFuncSetAttribute(pair_kernel, cudaFuncAttributeMaxDynamicSharedMemorySize, SM_DYN);

    pair_kernel<<<NPAIR, 512, SM_DYN>>>(prob, gal, bn_gamma, bn_beta,
                                        fc_w, fc_b, lbn_gamma, lbn_beta, out);
}